// round 1
// baseline (speedup 1.0000x reference)
#include <cuda_runtime.h>
#include <math.h>

#define B_ROWS 16384
#define DDIM   512
#define EEXP   16
#define HDIM   256
#define LOUT   64

// gates scratch (allocation-free rule: static __device__ array)
__device__ float g_gates[B_ROWS * EEXP];

__device__ __forceinline__ float softplusf(float z) {
    // stable softplus, matches jax.nn.softplus = max(z,0) + log1p(exp(-|z|))
    return (z > 0.f) ? (z + log1pf(expf(-z))) : log1pf(expf(z));
}

// ---------------------------------------------------------------------------
// Kernel A: noisy gating. One warp handles 2 rows (16 lanes per row = experts).
// w_gate / w_noise cached in SMEM (64 KB dynamic).
// ---------------------------------------------------------------------------
__global__ __launch_bounds__(256) void gating_kernel(
    const float* __restrict__ x, const float* __restrict__ noise,
    const float* __restrict__ wg, const float* __restrict__ wn)
{
    extern __shared__ float sw[];          // [512*16] gate | [512*16] noise
    float* swg = sw;
    float* swn = sw + DDIM * EEXP;
    for (int i = threadIdx.x; i < DDIM * EEXP; i += blockDim.x) {
        swg[i] = wg[i];
        swn[i] = wn[i];
    }
    __syncthreads();

    int warpId = threadIdx.x >> 5;
    int lane   = threadIdx.x & 31;
    int gl     = lane & 15;   // expert index
    int grp    = lane >> 4;   // which row of the pair

    int pair = blockIdx.x * 8 + warpId;
    if (pair >= B_ROWS / 2) return;
    int b = pair * 2 + grp;

    const float* xrow = x + (size_t)b * DDIM;
    float accG = 0.f, accN = 0.f;
    for (int d0 = 0; d0 < DDIM; d0 += 16) {
        float xv = xrow[d0 + gl];                       // coalesced 16 floats / group
        #pragma unroll
        for (int j = 0; j < 16; j++) {
            float xj = __shfl_sync(0xffffffffu, xv, j, 16);
            accG = fmaf(xj, swg[(d0 + j) * EEXP + gl], accG);
            accN = fmaf(xj, swn[(d0 + j) * EEXP + gl], accN);
        }
    }

    float stddev = softplusf(accN) + 0.01f;
    float logit  = fmaf(noise[(size_t)b * EEXP + gl], stddev, accG);

    // softmax across the 16-lane group
    float m = logit;
    #pragma unroll
    for (int o = 8; o; o >>= 1) m = fmaxf(m, __shfl_xor_sync(0xffffffffu, m, o, 16));
    float p = expf(logit - m);
    float s = p;
    #pragma unroll
    for (int o = 8; o; o >>= 1) s += __shfl_xor_sync(0xffffffffu, s, o, 16);
    float prob = p / s;

    // mean of softmax outputs (numerically, sum/16), threshold, renormalize
    float s2 = prob;
    #pragma unroll
    for (int o = 8; o; o >>= 1) s2 += __shfl_xor_sync(0xffffffffu, s2, o, 16);
    float meanw = s2 * (1.f / 16.f) - 1e-8f;
    float g = (prob >= meanw) ? prob : 0.f;
    float gs = g;
    #pragma unroll
    for (int o = 8; o; o >>= 1) gs += __shfl_xor_sync(0xffffffffu, gs, o, 16);

    g_gates[(size_t)b * EEXP + gl] = g / gs;
}

// ---------------------------------------------------------------------------
// Kernel B: fused expert MLP. CTA = (row-tile of 64, expert e).
// Phase 1: h = tanh(x[64,512] @ W1[e][512,256] + b1)  -> SMEM (transposed)
// Phase 2: y = h[64,256] @ W2[e][256,64] + b2; out = gate * y
// ---------------------------------------------------------------------------
#define BM  64
#define BK  32
#define PAD 4
#define LDA (BM + PAD)   // 68, keeps float4 alignment (68*4 bytes per row)

__global__ __launch_bounds__(256, 2) void moe_kernel(
    const float* __restrict__ x,
    const float* __restrict__ W1, const float* __restrict__ b1,
    const float* __restrict__ W2, const float* __restrict__ b2,
    float* __restrict__ out)
{
    extern __shared__ float smem[];
    float* sA  = smem;                    // [BK][LDA]   x tile, k-major
    float* sB  = smem + BK * LDA;         // [BK][HDIM]  W1 tile
    float* sHT = sB + BK * HDIM;          // [HDIM][LDA] tanh(h), h-major
    float* sW2 = sA;                      // phase-2 W2 tile aliases sA (2048 <= 2176)

    int e   = blockIdx.y;
    int m0  = blockIdx.x * BM;
    int tid = threadIdx.x;

    const float* xg  = x  + (size_t)m0 * DDIM;
    const float* W1e = W1 + (size_t)e * DDIM * HDIM;

    int tx = tid & 31;   // h-tile column group (8 cols each)
    int ty = tid >> 5;   // m group (8 rows each)

    float acc[8][8];
    #pragma unroll
    for (int i = 0; i < 8; i++)
        #pragma unroll
        for (int j = 0; j < 8; j++) acc[i][j] = 0.f;

    for (int k0 = 0; k0 < DDIM; k0 += BK) {
        // load x tile [64][32] -> sA[k][m] (transposed), float4 global reads
        #pragma unroll
        for (int i = 0; i < 2; i++) {
            int id = tid + i * 256;               // 0..511 float4s
            int m  = id >> 3;
            int kq = id & 7;
            float4 v = *(const float4*)(xg + (size_t)m * DDIM + k0 + kq * 4);
            sA[(kq * 4 + 0) * LDA + m] = v.x;
            sA[(kq * 4 + 1) * LDA + m] = v.y;
            sA[(kq * 4 + 2) * LDA + m] = v.z;
            sA[(kq * 4 + 3) * LDA + m] = v.w;
        }
        // load W1 tile [32][256]
        #pragma unroll
        for (int i = 0; i < 8; i++) {
            int id = tid + i * 256;               // 0..2047 float4s
            int k  = id >> 6;
            int hq = id & 63;
            ((float4*)sB)[(size_t)k * 64 + hq] =
                *(const float4*)(W1e + (size_t)(k0 + k) * HDIM + hq * 4);
        }
        __syncthreads();

        #pragma unroll
        for (int kk = 0; kk < BK; kk++) {
            float4 a0  = *(float4*)&sA[kk * LDA + ty * 8];
            float4 a1  = *(float4*)&sA[kk * LDA + ty * 8 + 4];
            float4 b0v = *(float4*)&sB[kk * HDIM + tx * 8];
            float4 b1v = *(float4*)&sB[kk * HDIM + tx * 8 + 4];
            float af[8] = {a0.x, a0.y, a0.z, a0.w, a1.x, a1.y, a1.z, a1.w};
            float bf[8] = {b0v.x, b0v.y, b0v.z, b0v.w, b1v.x, b1v.y, b1v.z, b1v.w};
            #pragma unroll
            for (int i = 0; i < 8; i++)
                #pragma unroll
                for (int j = 0; j < 8; j++)
                    acc[i][j] = fmaf(af[i], bf[j], acc[i][j]);
        }
        __syncthreads();
    }

    // tanh(acc + b1) -> sHT[h][m]
    {
        const float* b1e = b1 + (size_t)e * HDIM;
        #pragma unroll
        for (int j = 0; j < 8; j++) {
            float bb = b1e[tx * 8 + j];
            #pragma unroll
            for (int i = 0; i < 8; i++) {
                sHT[(size_t)(tx * 8 + j) * LDA + ty * 8 + i] = tanhf(acc[i][j] + bb);
            }
        }
    }
    __syncthreads();

    // ---------------- phase 2: [64,256] @ [256,64] ----------------
    int tx2 = tid & 15;   // l group (4 each)
    int ty2 = tid >> 4;   // m group (4 each)
    float acc2[4][4];
    #pragma unroll
    for (int i = 0; i < 4; i++)
        #pragma unroll
        for (int j = 0; j < 4; j++) acc2[i][j] = 0.f;

    const float* W2e = W2 + (size_t)e * HDIM * LOUT;
    for (int h0 = 0; h0 < HDIM; h0 += BK) {
        // load W2 tile [32][64]
        #pragma unroll
        for (int i = 0; i < 2; i++) {
            int id = tid + i * 256;               // 0..511 float4s
            int k  = id >> 4;
            int lq = id & 15;
            ((float4*)sW2)[id] = *(const float4*)(W2e + (size_t)(h0 + k) * LOUT + lq * 4);
        }
        __syncthreads();

        #pragma unroll
        for (int kk = 0; kk < BK; kk++) {
            float4 a  = *(float4*)&sHT[(size_t)(h0 + kk) * LDA + ty2 * 4];
            float4 bv = *(float4*)&sW2[kk * LOUT + tx2 * 4];
            float af[4] = {a.x, a.y, a.z, a.w};
            float bf[4] = {bv.x, bv.y, bv.z, bv.w};
            #pragma unroll
            for (int i = 0; i < 4; i++)
                #pragma unroll
                for (int j = 0; j < 4; j++)
                    acc2[i][j] = fmaf(af[i], bf[j], acc2[i][j]);
        }
        __syncthreads();
    }

    // epilogue: (acc2 + b2) * gate -> out[b, e, l]
    const float* b2e = b2 + (size_t)e * LOUT;
    float bb[4];
    #pragma unroll
    for (int j = 0; j < 4; j++) bb[j] = b2e[tx2 * 4 + j];

    #pragma unroll
    for (int i = 0; i < 4; i++) {
        int m = m0 + ty2 * 4 + i;
        float gate = g_gates[(size_t)m * EEXP + e];
        float4 o;
        o.x = (acc2[i][0] + bb[0]) * gate;
        o.y = (acc2[i][1] + bb[1]) * gate;
        o.z = (acc2[i][2] + bb[2]) * gate;
        o.w = (acc2[i][3] + bb[3]) * gate;
        *(float4*)(out + ((size_t)m * EEXP + e) * LOUT + tx2 * 4) = o;
    }
}

// ---------------------------------------------------------------------------
extern "C" void kernel_launch(void* const* d_in, const int* in_sizes, int n_in,
                              void* d_out, int out_size)
{
    const float* x       = (const float*)d_in[0];
    const float* noise   = (const float*)d_in[1];
    const float* w_gate  = (const float*)d_in[2];
    const float* w_noise = (const float*)d_in[3];
    const float* W1      = (const float*)d_in[4];
    const float* b1      = (const float*)d_in[5];
    const float* W2      = (const float*)d_in[6];
    const float* b2      = (const float*)d_in[7];
    float* out = (float*)d_out;

    const int gating_smem = 2 * DDIM * EEXP * sizeof(float);                  // 65536
    const int moe_smem    = (BK * LDA + BK * HDIM + HDIM * LDA) * sizeof(float); // 111104

    cudaFuncSetAttribute(gating_kernel, cudaFuncAttributeMaxDynamicSharedMemorySize, gating_smem);
    cudaFuncSetAttribute(moe_kernel,    cudaFuncAttributeMaxDynamicSharedMemorySize, moe_smem);

    gating_kernel<<<B_ROWS / 16, 256, gating_smem>>>(x, noise, w_gate, w_noise);
    moe_kernel<<<dim3(B_ROWS / BM, EEXP), 256, moe_smem>>>(x, W1, b1, W2, b2, out);
}

// round 3
// speedup vs baseline: 2.3673x; 2.3673x over previous
#include <cuda_runtime.h>
#include <cstdint>
#include <math.h>

#define B_ROWS 16384
#define DDIM   512
#define EEXP   16
#define HDIM   256
#define LOUT   64

// ---------------- device scratch (allocation-free rule) ----------------
__device__ float g_gates[B_ROWS * EEXP];
__device__ float g_W1T[EEXP * HDIM * DDIM];   // [E][H][D], tf32-rounded
__device__ float g_W2T[EEXP * LOUT * HDIM];   // [E][L][H], tf32-rounded

// ---------------- helpers ----------------
__device__ __forceinline__ uint32_t smem_u32_of(const void* p) {
    uint32_t a;
    asm("{ .reg .u64 t; cvta.to.shared.u64 t, %1; cvt.u32.u64 %0, t; }" : "=r"(a) : "l"(p));
    return a;
}
__device__ __forceinline__ uint32_t ftf32_bits(float x) {
    uint32_t u;
    asm("cvt.rna.tf32.f32 %0, %1;" : "=r"(u) : "f"(x));
    return u;
}
__device__ __forceinline__ float ftf32(float x) { return __uint_as_float(ftf32_bits(x)); }

__device__ __forceinline__ float tanh_fast(float x) {
    float e = __expf(2.f * x);
    return 1.f - __fdividef(2.f, e + 1.f);
}
__device__ __forceinline__ float softplusf(float z) {
    return (z > 0.f) ? (z + log1pf(expf(-z))) : log1pf(expf(z));
}

__device__ __forceinline__ void cp16(uint32_t dst, const void* src) {
    asm volatile("cp.async.ca.shared.global [%0], [%1], 16;" :: "r"(dst), "l"(src));
}
#define CP_COMMIT() asm volatile("cp.async.commit_group;" ::: "memory")
#define CP_WAIT(n)  asm volatile("cp.async.wait_group %0;" :: "n"(n) : "memory")

__device__ __forceinline__ void mma_tf32(float* c, const uint32_t* a, const uint32_t* b) {
    asm volatile(
        "mma.sync.aligned.m16n8k8.row.col.f32.tf32.tf32.f32 "
        "{%0,%1,%2,%3}, {%4,%5,%6,%7}, {%8,%9}, {%0,%1,%2,%3};"
        : "+f"(c[0]), "+f"(c[1]), "+f"(c[2]), "+f"(c[3])
        : "r"(a[0]), "r"(a[1]), "r"(a[2]), "r"(a[3]), "r"(b[0]), "r"(b[1]));
}

// ---------------------------------------------------------------------------
// Transpose (+ tf32 round): dst[e][c][r] = tf32(src[e][r][c])
// ---------------------------------------------------------------------------
__global__ void transpose_kernel(const float* __restrict__ src, float* __restrict__ dst,
                                 int R, int C)
{
    __shared__ float t[32][33];
    int e = blockIdx.z;
    const float* s = src + (size_t)e * R * C;
    float* d = dst + (size_t)e * R * C;
    int c0 = blockIdx.x * 32, r0 = blockIdx.y * 32;
    int tx = threadIdx.x, ty = threadIdx.y;
    #pragma unroll
    for (int i = 0; i < 32; i += 8)
        t[ty + i][tx] = ftf32(s[(size_t)(r0 + ty + i) * C + c0 + tx]);
    __syncthreads();
    #pragma unroll
    for (int i = 0; i < 32; i += 8)
        d[(size_t)(c0 + ty + i) * R + r0 + tx] = t[tx][ty + i];
}

// ---------------------------------------------------------------------------
// Gating (verified in R1): one warp handles 2 rows, fp32 exact path.
// ---------------------------------------------------------------------------
__global__ __launch_bounds__(256) void gating_kernel(
    const float* __restrict__ x, const float* __restrict__ noise,
    const float* __restrict__ wg, const float* __restrict__ wn)
{
    extern __shared__ float sw[];
    float* swg = sw;
    float* swn = sw + DDIM * EEXP;
    for (int i = threadIdx.x; i < DDIM * EEXP; i += blockDim.x) {
        swg[i] = wg[i];
        swn[i] = wn[i];
    }
    __syncthreads();

    int warpId = threadIdx.x >> 5;
    int lane   = threadIdx.x & 31;
    int gl     = lane & 15;
    int grp    = lane >> 4;

    int pair = blockIdx.x * 8 + warpId;
    if (pair >= B_ROWS / 2) return;
    int b = pair * 2 + grp;

    const float* xrow = x + (size_t)b * DDIM;
    float accG = 0.f, accN = 0.f;
    for (int d0 = 0; d0 < DDIM; d0 += 16) {
        float xv = xrow[d0 + gl];
        #pragma unroll
        for (int j = 0; j < 16; j++) {
            float xj = __shfl_sync(0xffffffffu, xv, j, 16);
            accG = fmaf(xj, swg[(d0 + j) * EEXP + gl], accG);
            accN = fmaf(xj, swn[(d0 + j) * EEXP + gl], accN);
        }
    }

    float stddev = softplusf(accN) + 0.01f;
    float logit  = fmaf(noise[(size_t)b * EEXP + gl], stddev, accG);

    float m = logit;
    #pragma unroll
    for (int o = 8; o; o >>= 1) m = fmaxf(m, __shfl_xor_sync(0xffffffffu, m, o, 16));
    float p = expf(logit - m);
    float s = p;
    #pragma unroll
    for (int o = 8; o; o >>= 1) s += __shfl_xor_sync(0xffffffffu, s, o, 16);
    float prob = p / s;

    float s2 = prob;
    #pragma unroll
    for (int o = 8; o; o >>= 1) s2 += __shfl_xor_sync(0xffffffffu, s2, o, 16);
    float meanw = s2 * (1.f / 16.f) - 1e-8f;
    float g = (prob >= meanw) ? prob : 0.f;
    float gs = g;
    #pragma unroll
    for (int o = 8; o; o >>= 1) gs += __shfl_xor_sync(0xffffffffu, gs, o, 16);

    g_gates[(size_t)b * EEXP + gl] = g / gs;
}

// ---------------------------------------------------------------------------
// Fused expert MLP: tf32 mma.sync (m16n8k8).
// CTA = (128 rows, expert e). 8 warps.
// Phase 1: C1[128,256] = x @ W1[e], warps 2x4 (64x64 tiles).
// h = tanh(C1 + b1) -> SMEM [128][260 pad].
// Phase 2: C2[128,64] = h @ W2T[e], warps 4x2 (32x32 tiles).
// ---------------------------------------------------------------------------
// byte offsets
#define SM_H     0            // 128*260*4 = 133120
#define SM_A0    133120       // 128*20*4  = 10240
#define SM_A1    143360
#define SM_B0    153600       // 256*20*4  = 20480
#define SM_B1    174080
#define SM_BIAS  194560       // 256f + 64f = 1280
#define SMEM_MOE 195840
#define SM_W2_0  SM_A0        // 64*36*4 = 9216 (reuses A region in phase 2)
#define SM_W2_1  (SM_A0 + 9216)

#define LDK1 20   // phase-1 tile stride (words), KC=16
#define LDH  260  // h tile stride (words)
#define LDW2 36   // W2 chunk stride (words), KC=32

__global__ __launch_bounds__(256, 1) void moe_kernel(
    const float* __restrict__ x,
    const float* __restrict__ b1, const float* __restrict__ b2,
    float* __restrict__ out)
{
    extern __shared__ char smem[];
    float* sH    = (float*)(smem + SM_H);
    float* sBias1 = (float*)(smem + SM_BIAS);
    float* sBias2 = sBias1 + HDIM;

    const int tid  = threadIdx.x;
    const int wid  = tid >> 5;
    const int lane = tid & 31;
    const int g    = lane >> 2;   // group (row within fragment)
    const int tig  = lane & 3;    // thread-in-group
    const int e    = blockIdx.y;
    const int m0   = blockIdx.x * 128;

    const uint32_t smem_b = smem_u32_of(smem);

    const float* xg  = x + (size_t)m0 * DDIM;
    const float* w1e = g_W1T + (size_t)e * HDIM * DDIM;
    const float* w2e = g_W2T + (size_t)e * LOUT * HDIM;

    // biases
    if (tid < HDIM) sBias1[tid] = b1[(size_t)e * HDIM + tid];
    if (tid < LOUT) sBias2[tid] = b2[(size_t)e * LOUT + tid];

    // ---------------- phase 1 ----------------
    const int wm = wid >> 2;      // 0..1
    const int wn = wid & 3;       // 0..3

    float acc[4][8][4];
    #pragma unroll
    for (int i = 0; i < 4; i++)
        #pragma unroll
        for (int j = 0; j < 8; j++)
            #pragma unroll
            for (int q = 0; q < 4; q++) acc[i][j][q] = 0.f;

    // chunk loader: KC=16 floats per row
    auto load_chunk1 = [&](int c, int buf) {
        uint32_t aBase = smem_b + (buf ? SM_A1 : SM_A0);
        uint32_t bBase = smem_b + (buf ? SM_B1 : SM_B0);
        #pragma unroll
        for (int t = 0; t < 2; t++) {
            int id = tid + t * 256;          // 0..511
            int r = id >> 2, q = id & 3;
            cp16(aBase + (uint32_t)(r * (LDK1 * 4) + q * 16),
                 xg + (size_t)r * DDIM + c * 16 + q * 4);
        }
        #pragma unroll
        for (int t = 0; t < 4; t++) {
            int id = tid + t * 256;          // 0..1023
            int r = id >> 2, q = id & 3;
            cp16(bBase + (uint32_t)(r * (LDK1 * 4) + q * 16),
                 w1e + (size_t)r * DDIM + c * 16 + q * 4);
        }
        CP_COMMIT();
    };

    load_chunk1(0, 0);

    for (int c = 0; c < 32; c++) {
        int buf = c & 1;
        if (c + 1 < 32) load_chunk1(c + 1, buf ^ 1);
        if (c + 1 < 32) { CP_WAIT(1); } else { CP_WAIT(0); }
        __syncthreads();

        const float* A  = (const float*)(smem + (buf ? SM_A1 : SM_A0));
        const float* Bt = (const float*)(smem + (buf ? SM_B1 : SM_B0));

        #pragma unroll
        for (int ks = 0; ks < 16; ks += 8) {
            uint32_t af[4][4];
            #pragma unroll
            for (int i = 0; i < 4; i++) {
                int rb = wm * 64 + i * 16 + g;
                af[i][0] = ftf32_bits(A[rb * LDK1 + ks + tig]);
                af[i][1] = ftf32_bits(A[(rb + 8) * LDK1 + ks + tig]);
                af[i][2] = ftf32_bits(A[rb * LDK1 + ks + tig + 4]);
                af[i][3] = ftf32_bits(A[(rb + 8) * LDK1 + ks + tig + 4]);
            }
            uint32_t bf[8][2];
            #pragma unroll
            for (int j = 0; j < 8; j++) {
                int nb = wn * 64 + j * 8 + g;
                bf[j][0] = __float_as_uint(Bt[nb * LDK1 + ks + tig]);
                bf[j][1] = __float_as_uint(Bt[nb * LDK1 + ks + tig + 4]);
            }
            #pragma unroll
            for (int i = 0; i < 4; i++)
                #pragma unroll
                for (int j = 0; j < 8; j++)
                    mma_tf32(acc[i][j], af[i], bf[j]);
        }
        __syncthreads();
    }

    // ---- phase-2 W2 prologue (overlap with tanh epilogue) ----
    auto load_w2 = [&](int c2, int buf) {
        uint32_t wBase = smem_b + (buf ? SM_W2_1 : SM_W2_0);
        #pragma unroll
        for (int t = 0; t < 2; t++) {
            int id = tid + t * 256;          // 0..511
            int r = id >> 3, q = id & 7;
            cp16(wBase + (uint32_t)(r * (LDW2 * 4) + q * 16),
                 w2e + (size_t)r * HDIM + c2 * 32 + q * 4);
        }
        CP_COMMIT();
    };
    load_w2(0, 0);

    // ---- tanh(C1 + b1) -> sH (tf32-rounded) ----
    #pragma unroll
    for (int i = 0; i < 4; i++) {
        int r0 = wm * 64 + i * 16 + g;
        #pragma unroll
        for (int j = 0; j < 8; j++) {
            int cc = wn * 64 + j * 8 + 2 * tig;
            float bb0 = sBias1[cc], bb1 = sBias1[cc + 1];
            sH[r0 * LDH + cc]           = __uint_as_float(ftf32_bits(tanh_fast(acc[i][j][0] + bb0)));
            sH[r0 * LDH + cc + 1]       = __uint_as_float(ftf32_bits(tanh_fast(acc[i][j][1] + bb1)));
            sH[(r0 + 8) * LDH + cc]     = __uint_as_float(ftf32_bits(tanh_fast(acc[i][j][2] + bb0)));
            sH[(r0 + 8) * LDH + cc + 1] = __uint_as_float(ftf32_bits(tanh_fast(acc[i][j][3] + bb1)));
        }
    }
    __syncthreads();

    // ---------------- phase 2 ----------------
    const int wm2 = wid >> 1;     // 0..3
    const int wn2 = wid & 1;      // 0..1

    float acc2[2][4][4];
    #pragma unroll
    for (int i = 0; i < 2; i++)
        #pragma unroll
        for (int j = 0; j < 4; j++)
            #pragma unroll
            for (int q = 0; q < 4; q++) acc2[i][j][q] = 0.f;

    for (int c2 = 0; c2 < 8; c2++) {
        int buf = c2 & 1;
        if (c2 + 1 < 8) load_w2(c2 + 1, buf ^ 1);
        if (c2 + 1 < 8) { CP_WAIT(1); } else { CP_WAIT(0); }
        __syncthreads();

        const float* W = (const float*)(smem + (buf ? SM_W2_1 : SM_W2_0));

        #pragma unroll
        for (int ks = 0; ks < 32; ks += 8) {
            int kg = c2 * 32 + ks;
            uint32_t af[2][4];
            #pragma unroll
            for (int i = 0; i < 2; i++) {
                int rb = wm2 * 32 + i * 16 + g;
                af[i][0] = __float_as_uint(sH[rb * LDH + kg + tig]);
                af[i][1] = __float_as_uint(sH[(rb + 8) * LDH + kg + tig]);
                af[i][2] = __float_as_uint(sH[rb * LDH + kg + tig + 4]);
                af[i][3] = __float_as_uint(sH[(rb + 8) * LDH + kg + tig + 4]);
            }
            uint32_t bf[4][2];
            #pragma unroll
            for (int j = 0; j < 4; j++) {
                int nb = wn2 * 32 + j * 8 + g;
                bf[j][0] = __float_as_uint(W[nb * LDW2 + ks + tig]);
                bf[j][1] = __float_as_uint(W[nb * LDW2 + ks + tig + 4]);
            }
            #pragma unroll
            for (int i = 0; i < 2; i++)
                #pragma unroll
                for (int j = 0; j < 4; j++)
                    mma_tf32(acc2[i][j], af[i], bf[j]);
        }
        __syncthreads();
    }

    // ---- epilogue: out = gate * (C2 + b2) ----
    #pragma unroll
    for (int i = 0; i < 2; i++) {
        int r0 = wm2 * 32 + i * 16 + g;
        int mA = m0 + r0, mB = mA + 8;
        float gateA = g_gates[(size_t)mA * EEXP + e];
        float gateB = g_gates[(size_t)mB * EEXP + e];
        float* opA = out + ((size_t)mA * EEXP + e) * LOUT;
        float* opB = out + ((size_t)mB * EEXP + e) * LOUT;
        #pragma unroll
        for (int j = 0; j < 4; j++) {
            int cc = wn2 * 32 + j * 8 + 2 * tig;
            float bb0 = sBias2[cc], bb1 = sBias2[cc + 1];
            float2 oA, oB;
            oA.x = (acc2[i][j][0] + bb0) * gateA;
            oA.y = (acc2[i][j][1] + bb1) * gateA;
            oB.x = (acc2[i][j][2] + bb0) * gateB;
            oB.y = (acc2[i][j][3] + bb1) * gateB;
            *(float2*)(opA + cc) = oA;
            *(float2*)(opB + cc) = oB;
        }
    }
}

// ---------------------------------------------------------------------------
extern "C" void kernel_launch(void* const* d_in, const int* in_sizes, int n_in,
                              void* d_out, int out_size)
{
    const float* x       = (const float*)d_in[0];
    const float* noise   = (const float*)d_in[1];
    const float* w_gate  = (const float*)d_in[2];
    const float* w_noise = (const float*)d_in[3];
    const float* W1      = (const float*)d_in[4];
    const float* b1      = (const float*)d_in[5];
    const float* W2      = (const float*)d_in[6];
    const float* b2      = (const float*)d_in[7];
    float* out = (float*)d_out;

    float* w1t; cudaGetSymbolAddress((void**)&w1t, g_W1T);
    float* w2t; cudaGetSymbolAddress((void**)&w2t, g_W2T);

    const int gating_smem = 2 * DDIM * EEXP * sizeof(float);  // 65536

    cudaFuncSetAttribute(gating_kernel, cudaFuncAttributeMaxDynamicSharedMemorySize, gating_smem);
    cudaFuncSetAttribute(moe_kernel,    cudaFuncAttributeMaxDynamicSharedMemorySize, SMEM_MOE);

    transpose_kernel<<<dim3(HDIM / 32, DDIM / 32, EEXP), dim3(32, 8)>>>(W1, w1t, DDIM, HDIM);
    transpose_kernel<<<dim3(LOUT / 32, HDIM / 32, EEXP), dim3(32, 8)>>>(W2, w2t, HDIM, LOUT);
    gating_kernel<<<B_ROWS / 16, 256, gating_smem>>>(x, noise, w_gate, w_noise);
    moe_kernel<<<dim3(B_ROWS / 128, EEXP), 256, SMEM_MOE>>>(x, b1, b2, out);
}

// round 4
// speedup vs baseline: 2.5350x; 1.0708x over previous
#include <cuda_runtime.h>
#include <cstdint>
#include <math.h>

#define B_ROWS 16384
#define DDIM   512
#define EEXP   16
#define HDIM   256
#define LOUT   64

// ---------------- device scratch (allocation-free rule) ----------------
__device__ float g_gates[B_ROWS * EEXP];
__device__ float g_Xr[B_ROWS * DDIM];         // x, tf32-rounded
__device__ float g_W1T[EEXP * HDIM * DDIM];   // [E][H][D], tf32-rounded
__device__ float g_W2T[EEXP * LOUT * HDIM];   // [E][L][H], tf32-rounded

// ---------------- helpers ----------------
__device__ __forceinline__ uint32_t smem_u32_of(const void* p) {
    uint32_t a;
    asm("{ .reg .u64 t; cvta.to.shared.u64 t, %1; cvt.u32.u64 %0, t; }" : "=r"(a) : "l"(p));
    return a;
}
__device__ __forceinline__ uint32_t ftf32_bits(float x) {
    uint32_t u;
    asm("cvt.rna.tf32.f32 %0, %1;" : "=r"(u) : "f"(x));
    return u;
}
__device__ __forceinline__ float ftf32(float x) { return __uint_as_float(ftf32_bits(x)); }

__device__ __forceinline__ float tanh_fast(float x) {
    float e = __expf(2.f * x);
    return 1.f - __fdividef(2.f, e + 1.f);
}
__device__ __forceinline__ float softplusf(float z) {
    return (z > 0.f) ? (z + log1pf(expf(-z))) : log1pf(expf(z));
}

__device__ __forceinline__ void cp16(uint32_t dst, const void* src) {
    asm volatile("cp.async.ca.shared.global [%0], [%1], 16;" :: "r"(dst), "l"(src));
}
#define CP_COMMIT() asm volatile("cp.async.commit_group;" ::: "memory")
#define CP_WAIT(n)  asm volatile("cp.async.wait_group %0;" :: "n"(n) : "memory")

#define LDMX4(r0, r1, r2, r3, addr) \
    asm volatile("ldmatrix.sync.aligned.m8n8.x4.shared.b16 {%0,%1,%2,%3}, [%4];" \
                 : "=r"(r0), "=r"(r1), "=r"(r2), "=r"(r3) : "r"(addr))

__device__ __forceinline__ void mma_tf32(float* c, const uint32_t* a, const uint32_t* b) {
    asm volatile(
        "mma.sync.aligned.m16n8k8.row.col.f32.tf32.tf32.f32 "
        "{%0,%1,%2,%3}, {%4,%5,%6,%7}, {%8,%9}, {%0,%1,%2,%3};"
        : "+f"(c[0]), "+f"(c[1]), "+f"(c[2]), "+f"(c[3])
        : "r"(a[0]), "r"(a[1]), "r"(a[2]), "r"(a[3]), "r"(b[0]), "r"(b[1]));
}

// ---------------------------------------------------------------------------
// x pre-round: g_Xr = tf32(x)
// ---------------------------------------------------------------------------
__global__ __launch_bounds__(256) void roundx_kernel(const float4* __restrict__ in,
                                                     float4* __restrict__ outv)
{
    int i = blockIdx.x * 256 + threadIdx.x;
    float4 v = in[i];
    v.x = ftf32(v.x); v.y = ftf32(v.y); v.z = ftf32(v.z); v.w = ftf32(v.w);
    outv[i] = v;
}

// ---------------------------------------------------------------------------
// Transpose (+ tf32 round): dst[e][c][r] = tf32(src[e][r][c])
// ---------------------------------------------------------------------------
__global__ void transpose_kernel(const float* __restrict__ src, float* __restrict__ dst,
                                 int R, int C)
{
    __shared__ float t[32][33];
    int e = blockIdx.z;
    const float* s = src + (size_t)e * R * C;
    float* d = dst + (size_t)e * R * C;
    int c0 = blockIdx.x * 32, r0 = blockIdx.y * 32;
    int tx = threadIdx.x, ty = threadIdx.y;
    #pragma unroll
    for (int i = 0; i < 32; i += 8)
        t[ty + i][tx] = ftf32(s[(size_t)(r0 + ty + i) * C + c0 + tx]);
    __syncthreads();
    #pragma unroll
    for (int i = 0; i < 32; i += 8)
        d[(size_t)(c0 + ty + i) * R + r0 + tx] = t[tx][ty + i];
}

// ---------------------------------------------------------------------------
// Gating (verified): one warp handles 2 rows, fp32 exact path.
// ---------------------------------------------------------------------------
__global__ __launch_bounds__(256) void gating_kernel(
    const float* __restrict__ x, const float* __restrict__ noise,
    const float* __restrict__ wg, const float* __restrict__ wn)
{
    extern __shared__ float sw[];
    float* swg = sw;
    float* swn = sw + DDIM * EEXP;
    for (int i = threadIdx.x; i < DDIM * EEXP; i += blockDim.x) {
        swg[i] = wg[i];
        swn[i] = wn[i];
    }
    __syncthreads();

    int warpId = threadIdx.x >> 5;
    int lane   = threadIdx.x & 31;
    int gl     = lane & 15;
    int grp    = lane >> 4;

    int pair = blockIdx.x * 8 + warpId;
    if (pair >= B_ROWS / 2) return;
    int b = pair * 2 + grp;

    const float* xrow = x + (size_t)b * DDIM;
    float accG = 0.f, accN = 0.f;
    for (int d0 = 0; d0 < DDIM; d0 += 16) {
        float xv = xrow[d0 + gl];
        #pragma unroll
        for (int j = 0; j < 16; j++) {
            float xj = __shfl_sync(0xffffffffu, xv, j, 16);
            accG = fmaf(xj, swg[(d0 + j) * EEXP + gl], accG);
            accN = fmaf(xj, swn[(d0 + j) * EEXP + gl], accN);
        }
    }

    float stddev = softplusf(accN) + 0.01f;
    float logit  = fmaf(noise[(size_t)b * EEXP + gl], stddev, accG);

    float m = logit;
    #pragma unroll
    for (int o = 8; o; o >>= 1) m = fmaxf(m, __shfl_xor_sync(0xffffffffu, m, o, 16));
    float p = expf(logit - m);
    float s = p;
    #pragma unroll
    for (int o = 8; o; o >>= 1) s += __shfl_xor_sync(0xffffffffu, s, o, 16);
    float prob = p / s;

    float s2 = prob;
    #pragma unroll
    for (int o = 8; o; o >>= 1) s2 += __shfl_xor_sync(0xffffffffu, s2, o, 16);
    float meanw = s2 * (1.f / 16.f) - 1e-8f;
    float g = (prob >= meanw) ? prob : 0.f;
    float gs = g;
    #pragma unroll
    for (int o = 8; o; o >>= 1) gs += __shfl_xor_sync(0xffffffffu, gs, o, 16);

    g_gates[(size_t)b * EEXP + gl] = g / gs;
}

// ---------------------------------------------------------------------------
// Fused expert MLP: tf32 mma.sync + ldmatrix fragment loads.
// CTA = (128 rows, expert e). 8 warps.
// Phase 1: C1[128,256] = x @ W1[e], warps 2x4 (64x64 tiles).
// h = tanh(C1 + b1) -> SMEM [128][260 pad], tf32-rounded.
// Phase 2: C2[128,64] = h @ W2T[e], warps 4x2 (32x32 tiles).
// ---------------------------------------------------------------------------
#define SM_H     0            // 128*260*4 = 133120
#define SM_A0    133120       // 128*20*4  = 10240
#define SM_A1    143360
#define SM_B0    153600       // 256*20*4  = 20480
#define SM_B1    174080
#define SM_BIAS  194560       // 256f + 64f = 1280
#define SMEM_MOE 195840
#define SM_W2_0  SM_A0        // 64*36*4 = 9216 (reuses A region in phase 2)
#define SM_W2_1  (SM_A0 + 9216)

#define LDK1 20   // phase-1 tile stride (words), KC=16
#define LDH  260  // h tile stride (words)
#define LDW2 36   // W2 chunk stride (words), KC=32

__global__ __launch_bounds__(256, 1) void moe_kernel(
    const float* __restrict__ b1, const float* __restrict__ b2,
    float* __restrict__ out)
{
    extern __shared__ char smem[];
    float* sH     = (float*)(smem + SM_H);
    float* sBias1 = (float*)(smem + SM_BIAS);
    float* sBias2 = sBias1 + HDIM;

    const int tid  = threadIdx.x;
    const int wid  = tid >> 5;
    const int lane = tid & 31;
    const int g    = lane >> 2;
    const int tig  = lane & 3;
    const int e    = blockIdx.y;
    const int m0   = blockIdx.x * 128;

    const uint32_t smem_b = smem_u32_of(smem);

    const float* xg  = g_Xr  + (size_t)m0 * DDIM;
    const float* w1e = g_W1T + (size_t)e * HDIM * DDIM;
    const float* w2e = g_W2T + (size_t)e * LOUT * HDIM;

    if (tid < HDIM) sBias1[tid] = b1[(size_t)e * HDIM + tid];
    if (tid < LOUT) sBias2[tid] = b2[(size_t)e * LOUT + tid];

    // lane-dependent ldmatrix offsets (bytes)
    const uint32_t offA  = (uint32_t)(((lane & 15) * LDK1 + (lane >> 4) * 4) * 4);
    const uint32_t offB  = (uint32_t)((((lane & 7) + ((lane >> 4) & 1) * 8) * LDK1) * 4 + ((lane >> 3) & 1) * 16);
    const uint32_t offA2 = (uint32_t)(((lane & 15) * LDH + (lane >> 4) * 4) * 4);
    const uint32_t offB2 = (uint32_t)((((lane & 7) + ((lane >> 4) & 1) * 8) * LDW2) * 4 + ((lane >> 3) & 1) * 16);

    // ---------------- phase 1 ----------------
    const int wm = wid >> 2;      // 0..1
    const int wn = wid & 3;       // 0..3

    float acc[4][8][4];
    #pragma unroll
    for (int i = 0; i < 4; i++)
        #pragma unroll
        for (int j = 0; j < 8; j++)
            #pragma unroll
            for (int q = 0; q < 4; q++) acc[i][j][q] = 0.f;

    auto load_chunk1 = [&](int c, int buf) {
        uint32_t aBase = smem_b + (buf ? SM_A1 : SM_A0);
        uint32_t bBase = smem_b + (buf ? SM_B1 : SM_B0);
        #pragma unroll
        for (int t = 0; t < 2; t++) {
            int id = tid + t * 256;          // 0..511
            int r = id >> 2, q = id & 3;
            cp16(aBase + (uint32_t)(r * (LDK1 * 4) + q * 16),
                 xg + (size_t)r * DDIM + c * 16 + q * 4);
        }
        #pragma unroll
        for (int t = 0; t < 4; t++) {
            int id = tid + t * 256;          // 0..1023
            int r = id >> 2, q = id & 3;
            cp16(bBase + (uint32_t)(r * (LDK1 * 4) + q * 16),
                 w1e + (size_t)r * DDIM + c * 16 + q * 4);
        }
        CP_COMMIT();
    };

    load_chunk1(0, 0);

    for (int c = 0; c < 32; c++) {
        int buf = c & 1;
        if (c + 1 < 32) load_chunk1(c + 1, buf ^ 1);
        if (c + 1 < 32) { CP_WAIT(1); } else { CP_WAIT(0); }
        __syncthreads();

        const uint32_t aB = smem_b + (buf ? SM_A1 : SM_A0);
        const uint32_t bB = smem_b + (buf ? SM_B1 : SM_B0);

        #pragma unroll
        for (int ks = 0; ks < 16; ks += 8) {
            uint32_t af[4][4];
            #pragma unroll
            for (int i = 0; i < 4; i++) {
                uint32_t ad = aB + (uint32_t)(((wm * 64 + i * 16) * LDK1 + ks) * 4) + offA;
                LDMX4(af[i][0], af[i][1], af[i][2], af[i][3], ad);
            }
            uint32_t bf[8][2];
            #pragma unroll
            for (int j2 = 0; j2 < 4; j2++) {
                uint32_t bd = bB + (uint32_t)(((wn * 64 + j2 * 16) * LDK1 + ks) * 4) + offB;
                LDMX4(bf[2 * j2][0], bf[2 * j2][1], bf[2 * j2 + 1][0], bf[2 * j2 + 1][1], bd);
            }
            #pragma unroll
            for (int i = 0; i < 4; i++)
                #pragma unroll
                for (int j = 0; j < 8; j++)
                    mma_tf32(acc[i][j], af[i], bf[j]);
        }
        __syncthreads();
    }

    // ---- phase-2 W2 prologue (overlap with tanh epilogue) ----
    auto load_w2 = [&](int c2, int buf) {
        uint32_t wBase = smem_b + (buf ? SM_W2_1 : SM_W2_0);
        #pragma unroll
        for (int t = 0; t < 2; t++) {
            int id = tid + t * 256;          // 0..511
            int r = id >> 3, q = id & 7;
            cp16(wBase + (uint32_t)(r * (LDW2 * 4) + q * 16),
                 w2e + (size_t)r * HDIM + c2 * 32 + q * 4);
        }
        CP_COMMIT();
    };
    load_w2(0, 0);

    // ---- tanh(C1 + b1) -> sH (tf32-rounded), float2 stores ----
    #pragma unroll
    for (int i = 0; i < 4; i++) {
        int r0 = wm * 64 + i * 16 + g;
        #pragma unroll
        for (int j = 0; j < 8; j++) {
            int cc = wn * 64 + j * 8 + 2 * tig;
            float bb0 = sBias1[cc], bb1 = sBias1[cc + 1];
            float2 vA, vB;
            vA.x = __uint_as_float(ftf32_bits(tanh_fast(acc[i][j][0] + bb0)));
            vA.y = __uint_as_float(ftf32_bits(tanh_fast(acc[i][j][1] + bb1)));
            vB.x = __uint_as_float(ftf32_bits(tanh_fast(acc[i][j][2] + bb0)));
            vB.y = __uint_as_float(ftf32_bits(tanh_fast(acc[i][j][3] + bb1)));
            *(float2*)&sH[r0 * LDH + cc]       = vA;
            *(float2*)&sH[(r0 + 8) * LDH + cc] = vB;
        }
    }
    __syncthreads();

    // ---------------- phase 2 ----------------
    const int wm2 = wid >> 1;     // 0..3
    const int wn2 = wid & 1;      // 0..1

    float acc2[2][4][4];
    #pragma unroll
    for (int i = 0; i < 2; i++)
        #pragma unroll
        for (int j = 0; j < 4; j++)
            #pragma unroll
            for (int q = 0; q < 4; q++) acc2[i][j][q] = 0.f;

    for (int c2 = 0; c2 < 8; c2++) {
        int buf = c2 & 1;
        if (c2 + 1 < 8) load_w2(c2 + 1, buf ^ 1);
        if (c2 + 1 < 8) { CP_WAIT(1); } else { CP_WAIT(0); }
        __syncthreads();

        const uint32_t wB = smem_b + (buf ? SM_W2_1 : SM_W2_0);
        const uint32_t hB = smem_b + SM_H;

        #pragma unroll
        for (int ks = 0; ks < 32; ks += 8) {
            int kg = c2 * 32 + ks;
            uint32_t af[2][4];
            #pragma unroll
            for (int i = 0; i < 2; i++) {
                uint32_t ad = hB + (uint32_t)(((wm2 * 32 + i * 16) * LDH + kg) * 4) + offA2;
                LDMX4(af[i][0], af[i][1], af[i][2], af[i][3], ad);
            }
            uint32_t bf[4][2];
            #pragma unroll
            for (int j2 = 0; j2 < 2; j2++) {
                uint32_t bd = wB + (uint32_t)(((wn2 * 32 + j2 * 16) * LDW2 + ks) * 4) + offB2;
                LDMX4(bf[2 * j2][0], bf[2 * j2][1], bf[2 * j2 + 1][0], bf[2 * j2 + 1][1], bd);
            }
            #pragma unroll
            for (int i = 0; i < 2; i++)
                #pragma unroll
                for (int j = 0; j < 4; j++)
                    mma_tf32(acc2[i][j], af[i], bf[j]);
        }
        __syncthreads();
    }

    // ---- epilogue: out = gate * (C2 + b2) ----
    #pragma unroll
    for (int i = 0; i < 2; i++) {
        int r0 = wm2 * 32 + i * 16 + g;
        int mA = m0 + r0, mB = mA + 8;
        float gateA = g_gates[(size_t)mA * EEXP + e];
        float gateB = g_gates[(size_t)mB * EEXP + e];
        float* opA = out + ((size_t)mA * EEXP + e) * LOUT;
        float* opB = out + ((size_t)mB * EEXP + e) * LOUT;
        #pragma unroll
        for (int j = 0; j < 4; j++) {
            int cc = wn2 * 32 + j * 8 + 2 * tig;
            float bb0 = sBias2[cc], bb1 = sBias2[cc + 1];
            float2 oA, oB;
            oA.x = (acc2[i][j][0] + bb0) * gateA;
            oA.y = (acc2[i][j][1] + bb1) * gateA;
            oB.x = (acc2[i][j][2] + bb0) * gateB;
            oB.y = (acc2[i][j][3] + bb1) * gateB;
            *(float2*)(opA + cc) = oA;
            *(float2*)(opB + cc) = oB;
        }
    }
}

// ---------------------------------------------------------------------------
extern "C" void kernel_launch(void* const* d_in, const int* in_sizes, int n_in,
                              void* d_out, int out_size)
{
    const float* x       = (const float*)d_in[0];
    const float* noise   = (const float*)d_in[1];
    const float* w_gate  = (const float*)d_in[2];
    const float* w_noise = (const float*)d_in[3];
    const float* W1      = (const float*)d_in[4];
    const float* b1      = (const float*)d_in[5];
    const float* W2      = (const float*)d_in[6];
    const float* b2      = (const float*)d_in[7];
    float* out = (float*)d_out;

    float* xr;  cudaGetSymbolAddress((void**)&xr,  g_Xr);
    float* w1t; cudaGetSymbolAddress((void**)&w1t, g_W1T);
    float* w2t; cudaGetSymbolAddress((void**)&w2t, g_W2T);

    const int gating_smem = 2 * DDIM * EEXP * sizeof(float);  // 65536

    cudaFuncSetAttribute(gating_kernel, cudaFuncAttributeMaxDynamicSharedMemorySize, gating_smem);
    cudaFuncSetAttribute(moe_kernel,    cudaFuncAttributeMaxDynamicSharedMemorySize, SMEM_MOE);

    roundx_kernel<<<B_ROWS * DDIM / 4 / 256, 256>>>((const float4*)x, (float4*)xr);
    transpose_kernel<<<dim3(HDIM / 32, DDIM / 32, EEXP), dim3(32, 8)>>>(W1, w1t, DDIM, HDIM);
    transpose_kernel<<<dim3(LOUT / 32, HDIM / 32, EEXP), dim3(32, 8)>>>(W2, w2t, HDIM, LOUT);
    gating_kernel<<<B_ROWS / 16, 256, gating_smem>>>(x, noise, w_gate, w_noise);
    moe_kernel<<<dim3(B_ROWS / 128, EEXP), 256, SMEM_MOE>>>(b1, b2, out);
}

// round 5
// speedup vs baseline: 4.5787x; 1.8062x over previous
#include <cuda_runtime.h>
#include <cuda_fp16.h>
#include <cstdint>
#include <math.h>

#define B_ROWS 16384
#define DDIM   512
#define EEXP   16
#define HDIM   256
#define LOUT   64

// ---------------- device scratch (allocation-free rule) ----------------
__device__ float  g_gates[B_ROWS * EEXP];
__device__ __half g_Xh [B_ROWS * DDIM];        // x, fp16
__device__ __half g_W1T[EEXP * HDIM * DDIM];   // [E][H][D], fp16
__device__ __half g_W2T[EEXP * LOUT * HDIM];   // [E][L][H], fp16

// ---------------- helpers ----------------
__device__ __forceinline__ uint32_t smem_u32_of(const void* p) {
    uint32_t a;
    asm("{ .reg .u64 t; cvta.to.shared.u64 t, %1; cvt.u32.u64 %0, t; }" : "=r"(a) : "l"(p));
    return a;
}
__device__ __forceinline__ float tanh_fast(float x) {
    float e = __expf(2.f * x);
    return 1.f - __fdividef(2.f, e + 1.f);
}
__device__ __forceinline__ float softplusf(float z) {
    return (z > 0.f) ? (z + log1pf(expf(-z))) : log1pf(expf(z));
}
__device__ __forceinline__ void cp16(uint32_t dst, const void* src) {
    asm volatile("cp.async.ca.shared.global [%0], [%1], 16;" :: "r"(dst), "l"(src));
}
#define CP_COMMIT() asm volatile("cp.async.commit_group;" ::: "memory")
#define CP_WAIT(n)  asm volatile("cp.async.wait_group %0;" :: "n"(n) : "memory")

#define LDMX4(r0, r1, r2, r3, addr) \
    asm volatile("ldmatrix.sync.aligned.m8n8.x4.shared.b16 {%0,%1,%2,%3}, [%4];" \
                 : "=r"(r0), "=r"(r1), "=r"(r2), "=r"(r3) : "r"(addr))

__device__ __forceinline__ void mma_f16(float* c, const uint32_t* a, const uint32_t* b) {
    asm volatile(
        "mma.sync.aligned.m16n8k16.row.col.f32.f16.f16.f32 "
        "{%0,%1,%2,%3}, {%4,%5,%6,%7}, {%8,%9}, {%0,%1,%2,%3};"
        : "+f"(c[0]), "+f"(c[1]), "+f"(c[2]), "+f"(c[3])
        : "r"(a[0]), "r"(a[1]), "r"(a[2]), "r"(a[3]), "r"(b[0]), "r"(b[1]));
}

// ---------------------------------------------------------------------------
// x -> fp16
// ---------------------------------------------------------------------------
__global__ __launch_bounds__(256) void convx_kernel(const float4* __restrict__ in,
                                                    __half2* __restrict__ outv)
{
    int i = blockIdx.x * 256 + threadIdx.x;
    float4 v = in[i];
    outv[2 * i]     = __floats2half2_rn(v.x, v.y);
    outv[2 * i + 1] = __floats2half2_rn(v.z, v.w);
}

// ---------------------------------------------------------------------------
// Transpose + fp16: dst[e][c][r] = half(src[e][r][c])
// ---------------------------------------------------------------------------
__global__ void transposeh_kernel(const float* __restrict__ src, __half* __restrict__ dst,
                                  int R, int C)
{
    __shared__ float t[32][33];
    int e = blockIdx.z;
    const float* s = src + (size_t)e * R * C;
    __half* d = dst + (size_t)e * R * C;
    int c0 = blockIdx.x * 32, r0 = blockIdx.y * 32;
    int tx = threadIdx.x, ty = threadIdx.y;
    #pragma unroll
    for (int i = 0; i < 32; i += 8)
        t[ty + i][tx] = s[(size_t)(r0 + ty + i) * C + c0 + tx];
    __syncthreads();
    #pragma unroll
    for (int i = 0; i < 32; i += 8)
        d[(size_t)(c0 + ty + i) * R + r0 + tx] = __float2half_rn(t[tx][ty + i]);
}

// ---------------------------------------------------------------------------
// Gating (fp32-exact path). 512 threads: 16 warps, warp = 2 rows.
// ---------------------------------------------------------------------------
__global__ __launch_bounds__(512) void gating_kernel(
    const float* __restrict__ x, const float* __restrict__ noise,
    const float* __restrict__ wg, const float* __restrict__ wn)
{
    extern __shared__ float sw[];
    float* swg = sw;
    float* swn = sw + DDIM * EEXP;
    for (int i = threadIdx.x; i < DDIM * EEXP; i += blockDim.x) {
        swg[i] = wg[i];
        swn[i] = wn[i];
    }
    __syncthreads();

    int warpId = threadIdx.x >> 5;
    int lane   = threadIdx.x & 31;
    int gl     = lane & 15;
    int grp    = lane >> 4;

    int pair = blockIdx.x * 16 + warpId;
    int b = pair * 2 + grp;

    const float* xrow = x + (size_t)b * DDIM;
    float accG = 0.f, accN = 0.f;
    for (int d0 = 0; d0 < DDIM; d0 += 16) {
        float xv = xrow[d0 + gl];
        #pragma unroll
        for (int j = 0; j < 16; j++) {
            float xj = __shfl_sync(0xffffffffu, xv, j, 16);
            accG = fmaf(xj, swg[(d0 + j) * EEXP + gl], accG);
            accN = fmaf(xj, swn[(d0 + j) * EEXP + gl], accN);
        }
    }

    float stddev = softplusf(accN) + 0.01f;
    float logit  = fmaf(noise[(size_t)b * EEXP + gl], stddev, accG);

    float m = logit;
    #pragma unroll
    for (int o = 8; o; o >>= 1) m = fmaxf(m, __shfl_xor_sync(0xffffffffu, m, o, 16));
    float p = expf(logit - m);
    float s = p;
    #pragma unroll
    for (int o = 8; o; o >>= 1) s += __shfl_xor_sync(0xffffffffu, s, o, 16);
    float prob = p / s;

    float s2 = prob;
    #pragma unroll
    for (int o = 8; o; o >>= 1) s2 += __shfl_xor_sync(0xffffffffu, s2, o, 16);
    float meanw = s2 * (1.f / 16.f) - 1e-8f;
    float g = (prob >= meanw) ? prob : 0.f;
    float gs = g;
    #pragma unroll
    for (int o = 8; o; o >>= 1) gs += __shfl_xor_sync(0xffffffffu, gs, o, 16);

    g_gates[(size_t)b * EEXP + gl] = g / gs;
}

// ---------------------------------------------------------------------------
// Fused expert MLP: fp16 mma.sync m16n8k16 + ldmatrix. 512 threads / 16 warps.
// CTA = (128 rows, expert e).
// Phase 1: C1[128,256] = x @ W1[e], warps 4x4 (32x64 tiles), K-chunks of 32.
// h = tanh(C1 + b1) -> SMEM fp16 [128][264 pad].
// Phase 2: C2[128,64] = h @ W2T[e], warps 4x4 (32x16 tiles).
// ---------------------------------------------------------------------------
// byte offsets (halves: 2B)
#define SM_H     0              // 128*264*2 = 67584
#define SM_A0    67584          // 128*40*2  = 10240
#define SM_A1    77824
#define SM_B0    88064          // 256*40*2  = 20480
#define SM_B1    108544
#define SM_BIAS  129024         // 256f + 64f = 1280
#define SMEM_MOE 130304
#define SM_W2_0  SM_A0          // 64*40*2 = 5120 (reuses A region in phase 2)
#define SM_W2_1  (SM_A0 + 5120)

#define LDK1 40   // phase-1 tile stride (halves), KC=32
#define LDH  264  // h tile stride (halves)
#define LDW2 40   // W2 chunk stride (halves), KC=32

__global__ __launch_bounds__(512, 1) void moe_kernel(
    const float* __restrict__ b1, const float* __restrict__ b2,
    float* __restrict__ out)
{
    extern __shared__ char smem[];
    __half* sH    = (__half*)(smem + SM_H);
    float* sBias1 = (float*)(smem + SM_BIAS);
    float* sBias2 = sBias1 + HDIM;

    const int tid  = threadIdx.x;
    const int wid  = tid >> 5;
    const int lane = tid & 31;
    const int g    = lane >> 2;
    const int tig  = lane & 3;
    const int e    = blockIdx.y;
    const int m0   = blockIdx.x * 128;

    const uint32_t smem_b = smem_u32_of(smem);

    const __half* xg  = g_Xh  + (size_t)m0 * DDIM;
    const __half* w1e = g_W1T + (size_t)e * HDIM * DDIM;
    const __half* w2e = g_W2T + (size_t)e * LOUT * HDIM;

    if (tid < HDIM) sBias1[tid] = b1[(size_t)e * HDIM + tid];
    if (tid < LOUT) sBias2[tid] = b2[(size_t)e * LOUT + tid];

    // ldmatrix lane-dependent byte offsets
    const uint32_t offA  = (uint32_t)((lane & 15) * (LDK1 * 2) + (lane >> 4) * 16);
    const uint32_t offB  = (uint32_t)(((lane & 7) + ((lane >> 4) & 1) * 8) * (LDK1 * 2) + ((lane >> 3) & 1) * 16);
    const uint32_t offA2 = (uint32_t)((lane & 15) * (LDH * 2) + (lane >> 4) * 16);
    const uint32_t offB2 = (uint32_t)(((lane & 7) + ((lane >> 4) & 1) * 8) * (LDW2 * 2) + ((lane >> 3) & 1) * 16);

    // ---------------- phase 1: 4x4 warp grid, 32x64 warp tiles ----------------
    const int wm = wid >> 2;      // 0..3 : rows 32*wm
    const int wn = wid & 3;       // 0..3 : cols 64*wn

    float acc[2][8][4];
    #pragma unroll
    for (int i = 0; i < 2; i++)
        #pragma unroll
        for (int j = 0; j < 8; j++)
            #pragma unroll
            for (int q = 0; q < 4; q++) acc[i][j][q] = 0.f;

    auto load_chunk1 = [&](int c, int buf) {
        uint32_t aBase = smem_b + (buf ? SM_A1 : SM_A0);
        uint32_t bBase = smem_b + (buf ? SM_B1 : SM_B0);
        {   // A: 128 rows x 32 halves = 512 cp16
            int r = tid >> 2, q = tid & 3;
            cp16(aBase + (uint32_t)(r * (LDK1 * 2) + q * 16),
                 xg + (size_t)r * DDIM + c * 32 + q * 8);
        }
        #pragma unroll
        for (int t = 0; t < 2; t++) {   // B: 256 rows x 32 halves = 1024 cp16
            int id = tid + t * 512;
            int r = id >> 2, q = id & 3;
            cp16(bBase + (uint32_t)(r * (LDK1 * 2) + q * 16),
                 w1e + (size_t)r * DDIM + c * 32 + q * 8);
        }
        CP_COMMIT();
    };

    load_chunk1(0, 0);

    for (int c = 0; c < 16; c++) {
        int buf = c & 1;
        if (c + 1 < 16) load_chunk1(c + 1, buf ^ 1);
        if (c + 1 < 16) { CP_WAIT(1); } else { CP_WAIT(0); }
        __syncthreads();

        const uint32_t aB = smem_b + (buf ? SM_A1 : SM_A0);
        const uint32_t bB = smem_b + (buf ? SM_B1 : SM_B0);

        #pragma unroll
        for (int ks = 0; ks < 32; ks += 16) {
            uint32_t af[2][4];
            #pragma unroll
            for (int i = 0; i < 2; i++) {
                uint32_t ad = aB + (uint32_t)(((wm * 32 + i * 16) * LDK1 + ks) * 2) + offA;
                LDMX4(af[i][0], af[i][1], af[i][2], af[i][3], ad);
            }
            uint32_t bf[8][2];
            #pragma unroll
            for (int j2 = 0; j2 < 4; j2++) {
                uint32_t bd = bB + (uint32_t)(((wn * 64 + j2 * 16) * LDK1 + ks) * 2) + offB;
                LDMX4(bf[2 * j2][0], bf[2 * j2][1], bf[2 * j2 + 1][0], bf[2 * j2 + 1][1], bd);
            }
            #pragma unroll
            for (int i = 0; i < 2; i++)
                #pragma unroll
                for (int j = 0; j < 8; j++)
                    mma_f16(acc[i][j], af[i], bf[j]);
        }
        __syncthreads();
    }

    // ---- phase-2 W2 prologue ----
    auto load_w2 = [&](int c2, int buf) {
        uint32_t wBase = smem_b + (buf ? SM_W2_1 : SM_W2_0);
        if (tid < 256) {     // 64 rows x 32 halves = 256 cp16
            int r = tid >> 2, q = tid & 3;
            cp16(wBase + (uint32_t)(r * (LDW2 * 2) + q * 16),
                 w2e + (size_t)r * HDIM + c2 * 32 + q * 8);
        }
        CP_COMMIT();
    };
    load_w2(0, 0);

    // ---- tanh(C1 + b1) -> sH (fp16), half2 stores ----
    #pragma unroll
    for (int i = 0; i < 2; i++) {
        int r0 = wm * 32 + i * 16 + g;
        #pragma unroll
        for (int j = 0; j < 8; j++) {
            int cc = wn * 64 + j * 8 + 2 * tig;
            float bb0 = sBias1[cc], bb1 = sBias1[cc + 1];
            *(__half2*)&sH[r0 * LDH + cc] =
                __floats2half2_rn(tanh_fast(acc[i][j][0] + bb0), tanh_fast(acc[i][j][1] + bb1));
            *(__half2*)&sH[(r0 + 8) * LDH + cc] =
                __floats2half2_rn(tanh_fast(acc[i][j][2] + bb0), tanh_fast(acc[i][j][3] + bb1));
        }
    }
    __syncthreads();

    // ---------------- phase 2: 4x4 warp grid, 32x16 warp tiles ----------------
    const int wm2 = wid >> 2;     // rows 32*wm2
    const int wn2 = wid & 3;      // cols 16*wn2

    float acc2[2][2][4];
    #pragma unroll
    for (int i = 0; i < 2; i++)
        #pragma unroll
        for (int j = 0; j < 2; j++)
            #pragma unroll
            for (int q = 0; q < 4; q++) acc2[i][j][q] = 0.f;

    const uint32_t hB = smem_b + SM_H;

    for (int c2 = 0; c2 < 8; c2++) {
        int buf = c2 & 1;
        if (c2 + 1 < 8) load_w2(c2 + 1, buf ^ 1);
        if (c2 + 1 < 8) { CP_WAIT(1); } else { CP_WAIT(0); }
        __syncthreads();

        const uint32_t wB = smem_b + (buf ? SM_W2_1 : SM_W2_0);

        #pragma unroll
        for (int ks = 0; ks < 32; ks += 16) {
            int kg = c2 * 32 + ks;
            uint32_t af[2][4];
            #pragma unroll
            for (int i = 0; i < 2; i++) {
                uint32_t ad = hB + (uint32_t)(((wm2 * 32 + i * 16) * LDH + kg) * 2) + offA2;
                LDMX4(af[i][0], af[i][1], af[i][2], af[i][3], ad);
            }
            uint32_t bf[2][2];
            {
                uint32_t bd = wB + (uint32_t)(((wn2 * 16) * LDW2 + ks) * 2) + offB2;
                LDMX4(bf[0][0], bf[0][1], bf[1][0], bf[1][1], bd);
            }
            #pragma unroll
            for (int i = 0; i < 2; i++)
                #pragma unroll
                for (int j = 0; j < 2; j++)
                    mma_f16(acc2[i][j], af[i], bf[j]);
        }
        __syncthreads();
    }

    // ---- epilogue: out = gate * (C2 + b2) ----
    #pragma unroll
    for (int i = 0; i < 2; i++) {
        int r0 = wm2 * 32 + i * 16 + g;
        int mA = m0 + r0, mB = mA + 8;
        float gateA = g_gates[(size_t)mA * EEXP + e];
        float gateB = g_gates[(size_t)mB * EEXP + e];
        float* opA = out + ((size_t)mA * EEXP + e) * LOUT;
        float* opB = out + ((size_t)mB * EEXP + e) * LOUT;
        #pragma unroll
        for (int j = 0; j < 2; j++) {
            int cc = wn2 * 16 + j * 8 + 2 * tig;
            float bb0 = sBias2[cc], bb1 = sBias2[cc + 1];
            float2 oA, oB;
            oA.x = (acc2[i][j][0] + bb0) * gateA;
            oA.y = (acc2[i][j][1] + bb1) * gateA;
            oB.x = (acc2[i][j][2] + bb0) * gateB;
            oB.y = (acc2[i][j][3] + bb1) * gateB;
            *(float2*)(opA + cc) = oA;
            *(float2*)(opB + cc) = oB;
        }
    }
}

// ---------------------------------------------------------------------------
extern "C" void kernel_launch(void* const* d_in, const int* in_sizes, int n_in,
                              void* d_out, int out_size)
{
    const float* x       = (const float*)d_in[0];
    const float* noise   = (const float*)d_in[1];
    const float* w_gate  = (const float*)d_in[2];
    const float* w_noise = (const float*)d_in[3];
    const float* W1      = (const float*)d_in[4];
    const float* b1      = (const float*)d_in[5];
    const float* W2      = (const float*)d_in[6];
    const float* b2      = (const float*)d_in[7];
    float* out = (float*)d_out;

    __half* xh;  cudaGetSymbolAddress((void**)&xh,  g_Xh);
    __half* w1t; cudaGetSymbolAddress((void**)&w1t, g_W1T);
    __half* w2t; cudaGetSymbolAddress((void**)&w2t, g_W2T);

    const int gating_smem = 2 * DDIM * EEXP * sizeof(float);  // 65536

    cudaFuncSetAttribute(gating_kernel, cudaFuncAttributeMaxDynamicSharedMemorySize, gating_smem);
    cudaFuncSetAttribute(moe_kernel,    cudaFuncAttributeMaxDynamicSharedMemorySize, SMEM_MOE);

    convx_kernel<<<B_ROWS * DDIM / 4 / 256, 256>>>((const float4*)x, (__half2*)xh);
    transposeh_kernel<<<dim3(HDIM / 32, DDIM / 32, EEXP), dim3(32, 8)>>>(W1, w1t, DDIM, HDIM);
    transposeh_kernel<<<dim3(LOUT / 32, HDIM / 32, EEXP), dim3(32, 8)>>>(W2, w2t, HDIM, LOUT);
    gating_kernel<<<B_ROWS / 32, 512, gating_smem>>>(x, noise, w_gate, w_noise);
    moe_kernel<<<dim3(B_ROWS / 128, EEXP), 512, SMEM_MOE>>>(b1, b2, out);
}